// round 1
// baseline (speedup 1.0000x reference)
#include <cuda_runtime.h>
#include <math.h>

#define NB 16
#define NC 256

// ---------------- scratch (device globals: no allocs allowed) ----------------
__device__ float g_A1[NB*NC*4096];
__device__ float g_D1[NB*NC*4096];
__device__ float g_A2[NB*NC*2048];
__device__ float g_D2[NB*NC*2048];
__device__ float g_A3[NB*NC*1024];
__device__ float g_D3[NB*NC*1024];
__device__ float g_H [NB*NC*4096];
__device__ float g_S [NB*NC*8192];

// ---------------- db4 filters ----------------
__constant__ float c_dec_lo[8] = {-0.010597401785069032f, 0.0328830116668852f, 0.030841381835560764f, -0.18703481171888114f, -0.027983769416859854f, 0.6308807679298589f, 0.7148465705529157f, 0.2303778133088965f};
__constant__ float c_dec_hi[8] = {-0.2303778133088965f, 0.7148465705529157f, -0.6308807679298589f, -0.027983769416859854f, 0.18703481171888114f, 0.030841381835560764f, -0.0328830116668852f, -0.010597401785069032f};
__constant__ float c_rec_lo[8] = {0.2303778133088965f, 0.7148465705529157f, 0.6308807679298589f, -0.027983769416859854f, -0.18703481171888114f, 0.030841381835560764f, 0.0328830116668852f, -0.010597401785069032f};
__constant__ float c_rec_hi[8] = {-0.010597401785069032f, -0.0328830116668852f, 0.030841381835560764f, 0.18703481171888114f, -0.027983769416859854f, -0.6308807679298589f, 0.7148465705529157f, -0.2303778133088965f};

// ---------------- DWT: a[j] = sum_t x[2j-3+t]*dec_lo[t], d likewise ----------------
__global__ __launch_bounds__(256) void dwt_kernel(const float* __restrict__ x,
                                                  float* __restrict__ a,
                                                  float* __restrict__ d,
                                                  int Lin) {
    int Lout = Lin >> 1;
    int row = blockIdx.y;                       // b*C + c
    const float* xr = x + (size_t)row * Lin;
    int j0 = blockIdx.x * 256;
    __shared__ float s[520];                    // x[2j0-3 .. 2j0+514] = 518 elems
    int base = 2 * j0 - 3;
    for (int i = threadIdx.x; i < 518; i += 256) {
        int idx = base + i;
        s[i] = (idx >= 0 && idx < Lin) ? xr[idx] : 0.f;
    }
    __syncthreads();
    int j = j0 + threadIdx.x;
    if (j < Lout) {
        int off = 2 * threadIdx.x;
        float sa = 0.f, sd = 0.f;
#pragma unroll
        for (int t = 0; t < 8; t++) {
            float v = s[off + t];
            sa = fmaf(v, c_dec_lo[t], sa);
            sd = fmaf(v, c_dec_hi[t], sd);
        }
        a[(size_t)row * Lout + j] = sa;
        d[(size_t)row * Lout + j] = sd;
    }
}

// ---------------- IDWT: y[n] = sum_{k:2k in [n-4,n+3]} a[k]*rec_lo[3+n-2k] + d[k]*rec_hi[...] ----------------
// optional fused skip add (last level)
__global__ __launch_bounds__(256) void idwt_kernel(const float* __restrict__ a,
                                                   const float* __restrict__ d,
                                                   const float* __restrict__ skip,
                                                   float* __restrict__ y,
                                                   int Lin) {
    int Lout = Lin * 2;
    int row = blockIdx.y;
    const float* ar = a + (size_t)row * Lin;
    const float* dr = d + (size_t)row * Lin;
    float* yr = y + (size_t)row * Lout;
    int m0 = blockIdx.x * 256;
    __shared__ float sa[260], sd[260];          // k = m0-2 .. m0+257
    for (int i = threadIdx.x; i < 260; i += 256) {
        int k = m0 - 2 + i;
        bool ok = (k >= 0 && k < Lin);
        sa[i] = ok ? ar[k] : 0.f;
        sd[i] = ok ? dr[k] : 0.f;
    }
    __syncthreads();
    int m = m0 + threadIdx.x;
    if (m < Lin) {
        int o = threadIdx.x;                    // sa index of k = m-2
        // even n=2m: k = m-2..m+1, filter idx 7,5,3,1
        float ye = sa[o]*c_rec_lo[7] + sa[o+1]*c_rec_lo[5] + sa[o+2]*c_rec_lo[3] + sa[o+3]*c_rec_lo[1]
                 + sd[o]*c_rec_hi[7] + sd[o+1]*c_rec_hi[5] + sd[o+2]*c_rec_hi[3] + sd[o+3]*c_rec_hi[1];
        // odd n=2m+1: k = m-1..m+2, filter idx 6,4,2,0
        float yo = sa[o+1]*c_rec_lo[6] + sa[o+2]*c_rec_lo[4] + sa[o+3]*c_rec_lo[2] + sa[o+4]*c_rec_lo[0]
                 + sd[o+1]*c_rec_hi[6] + sd[o+2]*c_rec_hi[4] + sd[o+3]*c_rec_hi[2] + sd[o+4]*c_rec_hi[0];
        int n = 2 * m;
        if (skip) { ye += skip[(size_t)row * Lout + n]; yo += skip[(size_t)row * Lout + n + 1]; }
        yr[n] = ye;
        yr[n + 1] = yo;
    }
}

// ---------------- GEMM res block: Out = f(W @ In_col + bias) [+ Res] ----------------
__device__ __forceinline__ float gelu_tanh(float x) {
    const float k0 = 0.7978845608028654f;  // sqrt(2/pi)
    const float k1 = 0.044715f;
    float x3 = x * x * x;
    float t = tanhf(k0 * (x + k1 * x3));
    return 0.5f * x * (1.f + t);
}

__device__ __forceinline__ void mm_compute(const float (*Ws)[128], const float (*Xs)[128],
                                           float acc[8][8], int ty, int tx) {
#pragma unroll
    for (int k = 0; k < 16; k++) {
        float ar[8], br[8];
        *(float4*)&ar[0] = *(const float4*)&Ws[k][ty * 4];
        *(float4*)&ar[4] = *(const float4*)&Ws[k][64 + ty * 4];
        *(float4*)&br[0] = *(const float4*)&Xs[k][tx * 4];
        *(float4*)&br[4] = *(const float4*)&Xs[k][64 + tx * 4];
#pragma unroll
        for (int i = 0; i < 8; i++)
#pragma unroll
            for (int j = 0; j < 8; j++)
                acc[i][j] = fmaf(ar[i], br[j], acc[i][j]);
    }
}

// mode 0: Out = gelu(acc + bias)          (hidden pass)
// mode 1: Out = Res + acc + bias          (output pass, residual)
__global__ __launch_bounds__(256) void resgemm_kernel(const float* __restrict__ In,
                                                      const float* __restrict__ W,
                                                      const float* __restrict__ bias,
                                                      const float* __restrict__ Res,
                                                      float* __restrict__ Out,
                                                      int L, int mode) {
    __shared__ float Ws[2][16][128];
    __shared__ float Xs[2][16][128];
    int tid = threadIdx.x;
    int tx = tid & 15, ty = tid >> 4;
    int b = blockIdx.z;
    int om = blockIdx.y * 128;
    int ln = blockIdx.x * 128;
    const float* Xb = In + (size_t)b * NC * L;

    // load-index precompute
    int xk = tid >> 5;            // 0..7
    int xl = (tid & 31) << 2;     // 0..124
    int wo = tid >> 2;            // 0..63
    int wk = (tid & 3) << 2;      // 0,4,8,12

    float acc[8][8];
#pragma unroll
    for (int i = 0; i < 8; i++)
#pragma unroll
        for (int j = 0; j < 8; j++) acc[i][j] = 0.f;

    float4 xr0, xr1, wr0, wr1;
    // prefetch tile 0
    xr0 = *(const float4*)&Xb[(size_t)xk * L + ln + xl];
    xr1 = *(const float4*)&Xb[(size_t)(xk + 8) * L + ln + xl];
    wr0 = *(const float4*)&W[(size_t)(om + wo) * NC + wk];
    wr1 = *(const float4*)&W[(size_t)(om + wo + 64) * NC + wk];

    int buf = 0;
    *(float4*)&Xs[buf][xk][xl] = xr0;
    *(float4*)&Xs[buf][xk + 8][xl] = xr1;
    Ws[buf][wk + 0][wo] = wr0.x; Ws[buf][wk + 1][wo] = wr0.y;
    Ws[buf][wk + 2][wo] = wr0.z; Ws[buf][wk + 3][wo] = wr0.w;
    Ws[buf][wk + 0][wo + 64] = wr1.x; Ws[buf][wk + 1][wo + 64] = wr1.y;
    Ws[buf][wk + 2][wo + 64] = wr1.z; Ws[buf][wk + 3][wo + 64] = wr1.w;
    __syncthreads();

#pragma unroll 1
    for (int t = 0; t < 16; t++) {
        if (t < 15) {
            int k0 = (t + 1) * 16;
            xr0 = *(const float4*)&Xb[(size_t)(k0 + xk) * L + ln + xl];
            xr1 = *(const float4*)&Xb[(size_t)(k0 + xk + 8) * L + ln + xl];
            wr0 = *(const float4*)&W[(size_t)(om + wo) * NC + k0 + wk];
            wr1 = *(const float4*)&W[(size_t)(om + wo + 64) * NC + k0 + wk];
        }
        mm_compute(Ws[buf], Xs[buf], acc, ty, tx);
        if (t < 15) {
            int nb = buf ^ 1;
            *(float4*)&Xs[nb][xk][xl] = xr0;
            *(float4*)&Xs[nb][xk + 8][xl] = xr1;
            Ws[nb][wk + 0][wo] = wr0.x; Ws[nb][wk + 1][wo] = wr0.y;
            Ws[nb][wk + 2][wo] = wr0.z; Ws[nb][wk + 3][wo] = wr0.w;
            Ws[nb][wk + 0][wo + 64] = wr1.x; Ws[nb][wk + 1][wo + 64] = wr1.y;
            Ws[nb][wk + 2][wo + 64] = wr1.z; Ws[nb][wk + 3][wo + 64] = wr1.w;
            __syncthreads();
            buf = nb;
        }
    }

    // epilogue (float4 stores, fused gelu or residual+bias)
#pragma unroll
    for (int ih = 0; ih < 2; ih++) {
#pragma unroll
        for (int ii = 0; ii < 4; ii++) {
            int i = ih * 4 + ii;
            int o = om + ih * 64 + ty * 4 + ii;
            float bb = bias[o];
            size_t rowoff = ((size_t)b * NC + o) * L + ln;
#pragma unroll
            for (int jh = 0; jh < 2; jh++) {
                int col = jh * 64 + tx * 4;
                float v0 = acc[i][jh * 4 + 0] + bb;
                float v1 = acc[i][jh * 4 + 1] + bb;
                float v2 = acc[i][jh * 4 + 2] + bb;
                float v3 = acc[i][jh * 4 + 3] + bb;
                if (mode == 0) {
                    v0 = gelu_tanh(v0); v1 = gelu_tanh(v1);
                    v2 = gelu_tanh(v2); v3 = gelu_tanh(v3);
                } else {
                    float4 r = *(const float4*)&Res[rowoff + col];
                    v0 += r.x; v1 += r.y; v2 += r.z; v3 += r.w;
                }
                float4 vv = make_float4(v0, v1, v2, v3);
                *(float4*)&Out[rowoff + col] = vv;
            }
        }
    }
}

// ---------------- LayerNorm over channel axis of [B, C, L] ----------------
__global__ __launch_bounds__(256) void ln_kernel(const float* __restrict__ S,
                                                 const float* __restrict__ g,
                                                 const float* __restrict__ bt,
                                                 float* __restrict__ out,
                                                 int L) {
    int b = blockIdx.y;
    int l0 = blockIdx.x * 64;
    int tx = threadIdx.x & 63;
    int ty = threadIdx.x >> 6;   // 0..3
    const float* Sb = S + (size_t)b * NC * L + l0;
    float sum = 0.f, sq = 0.f;
    for (int c = ty; c < NC; c += 4) {
        float v = Sb[(size_t)c * L + tx];
        sum += v;
        sq = fmaf(v, v, sq);
    }
    __shared__ float ssum[4][64], ssq[4][64];
    __shared__ float smu[64], srs[64];
    ssum[ty][tx] = sum;
    ssq[ty][tx] = sq;
    __syncthreads();
    if (ty == 0) {
        float s = ssum[0][tx] + ssum[1][tx] + ssum[2][tx] + ssum[3][tx];
        float q = ssq[0][tx] + ssq[1][tx] + ssq[2][tx] + ssq[3][tx];
        float mu = s * (1.f / NC);
        float var = q * (1.f / NC) - mu * mu;
        smu[tx] = mu;
        srs[tx] = rsqrtf(var + 1e-5f);
    }
    __syncthreads();
    float* Ob = out + (size_t)b * NC * L + l0;
    float mu = smu[tx], rs = srs[tx];
    for (int c = ty; c < NC; c += 4) {
        float v = Sb[(size_t)c * L + tx];
        Ob[(size_t)c * L + tx] = (v - mu) * rs * g[c] + bt[c];
    }
}

// ---------------- launch ----------------
static float* sym_addr(const void* sym) {
    void* p = nullptr;
    cudaGetSymbolAddress(&p, sym);
    return (float*)p;
}

extern "C" void kernel_launch(void* const* d_in, const int* in_sizes, int n_in,
                              void* d_out, int out_size) {
    const float* x     = (const float*)d_in[0];
    const float* ab_w1 = (const float*)d_in[1];
    const float* ab_b1 = (const float*)d_in[2];
    const float* ab_w2 = (const float*)d_in[3];
    const float* ab_b2 = (const float*)d_in[4];
    const float* db_w1 = (const float*)d_in[5];
    const float* db_b1 = (const float*)d_in[6];
    const float* db_w2 = (const float*)d_in[7];
    const float* db_b2 = (const float*)d_in[8];
    const float* ln_g  = (const float*)d_in[9];
    const float* ln_b  = (const float*)d_in[10];
    float* out = (float*)d_out;

    float* A1 = sym_addr(g_A1);
    float* D1 = sym_addr(g_D1);
    float* A2 = sym_addr(g_A2);
    float* D2 = sym_addr(g_D2);
    float* A3 = sym_addr(g_A3);
    float* D3 = sym_addr(g_D3);
    float* H  = sym_addr(g_H);
    float* S  = sym_addr(g_S);

    const int ROWS = NB * NC;   // 4096

    // ---- forward DWT chain ----
    dwt_kernel<<<dim3(4096 / 256, ROWS), 256>>>(x,  A1, D1, 8192);
    dwt_kernel<<<dim3(2048 / 256, ROWS), 256>>>(A1, A2, D2, 4096);
    dwt_kernel<<<dim3(1024 / 256, ROWS), 256>>>(A2, A3, D3, 2048);

    // ---- res blocks (in-place) ----
    auto resblock = [&](float* X, const float* w1, const float* b1,
                        const float* w2, const float* b2, int L) {
        dim3 grid(L / 128, 2, NB);
        resgemm_kernel<<<grid, 256>>>(X, w1, b1, nullptr, H, L, 0);
        resgemm_kernel<<<grid, 256>>>(H, w2, b2, X, X, L, 1);
    };
    resblock(D3, db_w1, db_b1, db_w2, db_b2, 1024);
    resblock(D2, db_w1, db_b1, db_w2, db_b2, 2048);
    resblock(D1, db_w1, db_b1, db_w2, db_b2, 4096);
    resblock(A3, ab_w1, ab_b1, ab_w2, ab_b2, 1024);

    // ---- inverse DWT chain (reuse A2, A1 as outputs; last fuses skip add) ----
    idwt_kernel<<<dim3(1024 / 256, ROWS), 256>>>(A3, D3, nullptr, A2, 1024);
    idwt_kernel<<<dim3(2048 / 256, ROWS), 256>>>(A2, D2, nullptr, A1, 2048);
    idwt_kernel<<<dim3(4096 / 256, ROWS), 256>>>(A1, D1, x,       S,  4096);

    // ---- layernorm over channels ----
    ln_kernel<<<dim3(8192 / 64, NB), 256>>>(S, ln_g, ln_b, out, 8192);
}

// round 3
// speedup vs baseline: 1.7995x; 1.7995x over previous
#include <cuda_runtime.h>
#include <cstdint>
#include <math.h>

#define NB 16
#define NC 256

// ---------------- scratch (device globals: no allocs allowed) ----------------
__device__ float g_A1[NB*NC*4096];
__device__ float g_D1[NB*NC*4096];
__device__ float g_A2[NB*NC*2048];
__device__ float g_D2[NB*NC*2048];
__device__ float g_A3[NB*NC*1024];
__device__ float g_D3[NB*NC*1024];
__device__ float g_H [NB*NC*4096];
__device__ float g_S [NB*NC*8192];
__device__ float g_Wr[4*NC*NC];     // tf32-rounded weights: ab_w1, ab_w2, db_w1, db_w2

// ---------------- db4 filters ----------------
__constant__ float c_dec_lo[8] = {-0.010597401785069032f, 0.0328830116668852f, 0.030841381835560764f, -0.18703481171888114f, -0.027983769416859854f, 0.6308807679298589f, 0.7148465705529157f, 0.2303778133088965f};
__constant__ float c_dec_hi[8] = {-0.2303778133088965f, 0.7148465705529157f, -0.6308807679298589f, -0.027983769416859854f, 0.18703481171888114f, 0.030841381835560764f, -0.0328830116668852f, -0.010597401785069032f};
__constant__ float c_rec_lo[8] = {0.2303778133088965f, 0.7148465705529157f, 0.6308807679298589f, -0.027983769416859854f, -0.18703481171888114f, 0.030841381835560764f, 0.0328830116668852f, -0.010597401785069032f};
__constant__ float c_rec_hi[8] = {-0.010597401785069032f, -0.0328830116668852f, 0.030841381835560764f, 0.18703481171888114f, -0.027983769416859854f, -0.6308807679298589f, 0.7148465705529157f, -0.2303778133088965f};

// ================= helpers =================
__device__ __forceinline__ uint32_t smem_u32(const void* p) {
    uint32_t a;
    asm("{ .reg .u64 t; cvta.to.shared.u64 t, %1; cvt.u32.u64 %0, t; }" : "=r"(a) : "l"(p));
    return a;
}
__device__ __forceinline__ void cp16(uint32_t dst, const void* src) {
    asm volatile("cp.async.cg.shared.global [%0], [%1], 16;" :: "r"(dst), "l"(src));
}
__device__ __forceinline__ void cp_commit() { asm volatile("cp.async.commit_group;" ::: "memory"); }
__device__ __forceinline__ void cp_wait2()  { asm volatile("cp.async.wait_group 2;" ::: "memory"); }

__device__ __forceinline__ void mma_tf32(float* c, const uint32_t* a, const uint32_t* b) {
    asm volatile("mma.sync.aligned.m16n8k8.row.col.f32.tf32.tf32.f32 "
                 "{%0,%1,%2,%3}, {%4,%5,%6,%7}, {%8,%9}, {%0,%1,%2,%3};"
                 : "+f"(c[0]), "+f"(c[1]), "+f"(c[2]), "+f"(c[3])
                 : "r"(a[0]), "r"(a[1]), "r"(a[2]), "r"(a[3]), "r"(b[0]), "r"(b[1]));
}

// smem layout per stage: A[128][36] floats then B[32][136] floats
#define A_STRIDE 36
#define B_STRIDE 136
#define A_FLOATS (128*A_STRIDE)
#define B_FLOATS (32*B_STRIDE)
#define STAGE_F  (A_FLOATS + B_FLOATS)
#define STAGE_BYTES (STAGE_F*4)
#define SMEM_DYN (3*STAGE_BYTES)

// ---------------- round weights to tf32 ----------------
__global__ __launch_bounds__(256) void roundw_kernel(const float* __restrict__ w0,
                                                     const float* __restrict__ w1,
                                                     const float* __restrict__ w2,
                                                     const float* __restrict__ w3,
                                                     float* __restrict__ out) {
    int i = blockIdx.x * 256 + threadIdx.x;  // 16384 threads, one float4 per matrix
    const float* src[4] = {w0, w1, w2, w3};
    for (int m = 0; m < 4; m++) {
        float4 v = *(const float4*)(src[m] + i * 4);
        uint32_t r0, r1, r2, r3;
        asm("cvt.rna.tf32.f32 %0, %1;" : "=r"(r0) : "f"(v.x));
        asm("cvt.rna.tf32.f32 %0, %1;" : "=r"(r1) : "f"(v.y));
        asm("cvt.rna.tf32.f32 %0, %1;" : "=r"(r2) : "f"(v.z));
        asm("cvt.rna.tf32.f32 %0, %1;" : "=r"(r3) : "f"(v.w));
        float4 o = make_float4(__uint_as_float(r0), __uint_as_float(r1),
                               __uint_as_float(r2), __uint_as_float(r3));
        *(float4*)(out + m * NC * NC + i * 4) = o;
    }
}

// ---------------- DWT ----------------
__global__ __launch_bounds__(256) void dwt_kernel(const float* __restrict__ x,
                                                  float* __restrict__ a,
                                                  float* __restrict__ d,
                                                  int Lin) {
    int Lout = Lin >> 1;
    int row = blockIdx.y;
    const float* xr = x + (size_t)row * Lin;
    int j0 = blockIdx.x * 256;
    __shared__ float s[520];
    int base = 2 * j0 - 3;
    for (int i = threadIdx.x; i < 518; i += 256) {
        int idx = base + i;
        s[i] = (idx >= 0 && idx < Lin) ? xr[idx] : 0.f;
    }
    __syncthreads();
    int j = j0 + threadIdx.x;
    if (j < Lout) {
        int off = 2 * threadIdx.x;
        float sa = 0.f, sd = 0.f;
#pragma unroll
        for (int t = 0; t < 8; t++) {
            float v = s[off + t];
            sa = fmaf(v, c_dec_lo[t], sa);
            sd = fmaf(v, c_dec_hi[t], sd);
        }
        a[(size_t)row * Lout + j] = sa;
        d[(size_t)row * Lout + j] = sd;
    }
}

// ---------------- IDWT (optional fused skip) ----------------
__global__ __launch_bounds__(256) void idwt_kernel(const float* __restrict__ a,
                                                   const float* __restrict__ d,
                                                   const float* __restrict__ skip,
                                                   float* __restrict__ y,
                                                   int Lin) {
    int Lout = Lin * 2;
    int row = blockIdx.y;
    const float* ar = a + (size_t)row * Lin;
    const float* dr = d + (size_t)row * Lin;
    float* yr = y + (size_t)row * Lout;
    int m0 = blockIdx.x * 256;
    __shared__ float sa[260], sd[260];
    for (int i = threadIdx.x; i < 260; i += 256) {
        int k = m0 - 2 + i;
        bool ok = (k >= 0 && k < Lin);
        sa[i] = ok ? ar[k] : 0.f;
        sd[i] = ok ? dr[k] : 0.f;
    }
    __syncthreads();
    int m = m0 + threadIdx.x;
    if (m < Lin) {
        int o = threadIdx.x;
        float ye = sa[o]*c_rec_lo[7] + sa[o+1]*c_rec_lo[5] + sa[o+2]*c_rec_lo[3] + sa[o+3]*c_rec_lo[1]
                 + sd[o]*c_rec_hi[7] + sd[o+1]*c_rec_hi[5] + sd[o+2]*c_rec_hi[3] + sd[o+3]*c_rec_hi[1];
        float yo = sa[o+1]*c_rec_lo[6] + sa[o+2]*c_rec_lo[4] + sa[o+3]*c_rec_lo[2] + sa[o+4]*c_rec_lo[0]
                 + sd[o+1]*c_rec_hi[6] + sd[o+2]*c_rec_hi[4] + sd[o+3]*c_rec_hi[2] + sd[o+4]*c_rec_hi[0];
        int n = 2 * m;
        if (skip) { ye += skip[(size_t)row * Lout + n]; yo += skip[(size_t)row * Lout + n + 1]; }
        yr[n] = ye;
        yr[n + 1] = yo;
    }
}

// ---------------- gelu ----------------
__device__ __forceinline__ float gelu_tanh(float x) {
    const float k0 = 0.7978845608028654f;
    const float k1 = 0.044715f;
    float x3 = x * x * x;
    float t = tanhf(k0 * (x + k1 * x3));
    return 0.5f * x * (1.f + t);
}

// ---------------- tf32 mma.sync GEMM: Out = f(W @ In + b) [+Res] ----------------
// CTA tile M=128 (out-ch), N=128 (l), K=256. 8 warps, each 64x32.
// A = W rows (tf32-pre-rounded), B = In (cvt.rna on fragments).
__global__ __launch_bounds__(256) void gemm_tc(const float* __restrict__ In,
                                               const float* __restrict__ Wr,
                                               const float* __restrict__ bias,
                                               const float* __restrict__ Res,
                                               float* __restrict__ Out,
                                               int L, int mode) {
    extern __shared__ float sm[];
    uint32_t smem_base = smem_u32(sm);
    int tid = threadIdx.x;
    int wid = tid >> 5, lane = tid & 31;
    int wm = wid >> 2;          // 0..1 : m block of 64
    int wn = wid & 3;           // 0..3 : n block of 32
    int g = lane >> 2;          // 0..7
    int tt = lane & 3;          // 0..3

    int b  = blockIdx.z;
    int om = blockIdx.y * 128;
    int ln = blockIdx.x * 128;

    const float* Wm  = Wr + (size_t)om * NC;
    const float* Inb = In + (size_t)b * NC * L + ln;

    float acc[4][4][4];
#pragma unroll
    for (int mt = 0; mt < 4; mt++)
#pragma unroll
        for (int nt = 0; nt < 4; nt++)
#pragma unroll
            for (int r = 0; r < 4; r++) acc[mt][nt][r] = 0.f;

    auto load_chunk = [&](int t, int s) {
        uint32_t Ab = smem_base + s * STAGE_BYTES;
        uint32_t Bb = Ab + A_FLOATS * 4;
        const float* wsrc = Wm + t * 32;
        const float* isrc = Inb + (size_t)(t * 32) * L;
#pragma unroll
        for (int i = 0; i < 4; i++) {        // A: 128 rows x 32 floats
            int idx = tid + i * 256;
            int r = idx >> 3, c = idx & 7;
            cp16(Ab + (uint32_t)(r * A_STRIDE + c * 4) * 4, wsrc + (size_t)r * NC + c * 4);
        }
#pragma unroll
        for (int i = 0; i < 4; i++) {        // B: 32 k-rows x 128 floats
            int idx = tid + i * 256;
            int k = idx >> 5, n = idx & 31;
            cp16(Bb + (uint32_t)(k * B_STRIDE + n * 4) * 4, isrc + (size_t)k * L + n * 4);
        }
    };

    // prologue: 3 stages
#pragma unroll
    for (int pt = 0; pt < 3; pt++) { load_chunk(pt, pt); cp_commit(); }

#pragma unroll 1
    for (int t = 0; t < 8; t++) {
        int s = t - (t >= 6 ? 6 : (t >= 3 ? 3 : 0));   // t % 3
        cp_wait2();
        __syncthreads();

        const float* As = sm + s * STAGE_F;
        const float* Bs = As + A_FLOATS;
        const float* Asw = As + (wm * 64 + g) * A_STRIDE;
        const float* Bsw = Bs + wn * 32 + g;
#pragma unroll
        for (int kk = 0; kk < 4; kk++) {
            int k = kk * 8 + tt;
            uint32_t a[4][4];
#pragma unroll
            for (int mt = 0; mt < 4; mt++) {
                const float* ap = Asw + mt * 16 * A_STRIDE + k;
                a[mt][0] = __float_as_uint(ap[0]);
                a[mt][1] = __float_as_uint(ap[8 * A_STRIDE]);
                a[mt][2] = __float_as_uint(ap[4]);
                a[mt][3] = __float_as_uint(ap[8 * A_STRIDE + 4]);
            }
            uint32_t bf[4][2];
#pragma unroll
            for (int nt = 0; nt < 4; nt++) {
                const float* bp = Bsw + k * B_STRIDE + nt * 8;
                float f0 = bp[0], f1 = bp[4 * B_STRIDE];
                asm("cvt.rna.tf32.f32 %0, %1;" : "=r"(bf[nt][0]) : "f"(f0));
                asm("cvt.rna.tf32.f32 %0, %1;" : "=r"(bf[nt][1]) : "f"(f1));
            }
#pragma unroll
            for (int mt = 0; mt < 4; mt++)
#pragma unroll
                for (int nt = 0; nt < 4; nt++)
                    mma_tf32(acc[mt][nt], a[mt], bf[nt]);
        }
        __syncthreads();
        if (t < 5) load_chunk(t + 3, s);
        cp_commit();
    }

    // ---- epilogue: fragments -> gmem directly (float2 pairs) ----
#pragma unroll
    for (int mt = 0; mt < 4; mt++) {
        int r0 = wm * 64 + mt * 16 + g;
#pragma unroll
        for (int half = 0; half < 2; half++) {
            int r = r0 + half * 8;
            int o = om + r;
            float bb = bias[o];
            size_t orow = ((size_t)b * NC + o) * L + ln;
#pragma unroll
            for (int nt = 0; nt < 4; nt++) {
                int col = wn * 32 + nt * 8 + tt * 2;
                float v0 = acc[mt][nt][half * 2 + 0] + bb;
                float v1 = acc[mt][nt][half * 2 + 1] + bb;
                if (mode == 0) {
                    v0 = gelu_tanh(v0);
                    v1 = gelu_tanh(v1);
                } else {
                    float2 rr = *(const float2*)&Res[orow + col];
                    v0 += rr.x; v1 += rr.y;
                }
                *(float2*)&Out[orow + col] = make_float2(v0, v1);
            }
        }
    }
}

// ---------------- LayerNorm over channels ----------------
__global__ __launch_bounds__(256) void ln_kernel(const float* __restrict__ S,
                                                 const float* __restrict__ g,
                                                 const float* __restrict__ bt,
                                                 float* __restrict__ out,
                                                 int L) {
    int b = blockIdx.y;
    int l0 = blockIdx.x * 64;
    int tx = threadIdx.x & 63;
    int ty = threadIdx.x >> 6;
    const float* Sb = S + (size_t)b * NC * L + l0;
    float sum = 0.f, sq = 0.f;
    for (int c = ty; c < NC; c += 4) {
        float v = Sb[(size_t)c * L + tx];
        sum += v;
        sq = fmaf(v, v, sq);
    }
    __shared__ float ssum[4][64], ssq[4][64];
    __shared__ float smu[64], srs[64];
    ssum[ty][tx] = sum;
    ssq[ty][tx] = sq;
    __syncthreads();
    if (ty == 0) {
        float s = ssum[0][tx] + ssum[1][tx] + ssum[2][tx] + ssum[3][tx];
        float q = ssq[0][tx] + ssq[1][tx] + ssq[2][tx] + ssq[3][tx];
        float mu = s * (1.f / NC);
        float var = q * (1.f / NC) - mu * mu;
        smu[tx] = mu;
        srs[tx] = rsqrtf(var + 1e-5f);
    }
    __syncthreads();
    float* Ob = out + (size_t)b * NC * L + l0;
    float mu = smu[tx], rs = srs[tx];
    for (int c = ty; c < NC; c += 4) {
        float v = Sb[(size_t)c * L + tx];
        Ob[(size_t)c * L + tx] = (v - mu) * rs * g[c] + bt[c];
    }
}

// ---------------- launch ----------------
static float* sym_addr(const void* sym) {
    void* p = nullptr;
    cudaGetSymbolAddress(&p, sym);
    return (float*)p;
}

extern "C" void kernel_launch(void* const* d_in, const int* in_sizes, int n_in,
                              void* d_out, int out_size) {
    const float* x     = (const float*)d_in[0];
    const float* ab_w1 = (const float*)d_in[1];
    const float* ab_b1 = (const float*)d_in[2];
    const float* ab_w2 = (const float*)d_in[3];
    const float* ab_b2 = (const float*)d_in[4];
    const float* db_w1 = (const float*)d_in[5];
    const float* db_b1 = (const float*)d_in[6];
    const float* db_w2 = (const float*)d_in[7];
    const float* db_b2 = (const float*)d_in[8];
    const float* ln_g  = (const float*)d_in[9];
    const float* ln_b  = (const float*)d_in[10];
    float* out = (float*)d_out;

    float* A1 = sym_addr(g_A1);
    float* D1 = sym_addr(g_D1);
    float* A2 = sym_addr(g_A2);
    float* D2 = sym_addr(g_D2);
    float* A3 = sym_addr(g_A3);
    float* D3 = sym_addr(g_D3);
    float* H  = sym_addr(g_H);
    float* S  = sym_addr(g_S);
    float* Wr = sym_addr(g_Wr);

    cudaFuncSetAttribute(gemm_tc, cudaFuncAttributeMaxDynamicSharedMemorySize, SMEM_DYN);

    const int ROWS = NB * NC;   // 4096

    // weight tf32 rounding (ab_w1, ab_w2, db_w1, db_w2)
    roundw_kernel<<<64, 256>>>(ab_w1, ab_w2, db_w1, db_w2, Wr);

    // forward DWT chain
    dwt_kernel<<<dim3(4096 / 256, ROWS), 256>>>(x,  A1, D1, 8192);
    dwt_kernel<<<dim3(2048 / 256, ROWS), 256>>>(A1, A2, D2, 4096);
    dwt_kernel<<<dim3(1024 / 256, ROWS), 256>>>(A2, A3, D3, 2048);

    // res blocks on tensor cores (mma.sync tf32)
    auto resblock = [&](float* X, const float* w1r, const float* b1,
                        const float* w2r, const float* b2, int L) {
        dim3 grid(L / 128, 2, NB);
        gemm_tc<<<grid, 256, SMEM_DYN>>>(X, w1r, b1, nullptr, H, L, 0);
        gemm_tc<<<grid, 256, SMEM_DYN>>>(H, w2r, b2, X, X, L, 1);
    };
    resblock(D3, Wr + 2*NC*NC, db_b1, Wr + 3*NC*NC, db_b2, 1024);
    resblock(D2, Wr + 2*NC*NC, db_b1, Wr + 3*NC*NC, db_b2, 2048);
    resblock(D1, Wr + 2*NC*NC, db_b1, Wr + 3*NC*NC, db_b2, 4096);
    resblock(A3, Wr + 0*NC*NC, ab_b1, Wr + 1*NC*NC, ab_b2, 1024);

    // inverse DWT chain (last level fuses skip add)
    idwt_kernel<<<dim3(1024 / 256, ROWS), 256>>>(A3, D3, nullptr, A2, 1024);
    idwt_kernel<<<dim3(2048 / 256, ROWS), 256>>>(A2, D2, nullptr, A1, 2048);
    idwt_kernel<<<dim3(4096 / 256, ROWS), 256>>>(A1, D1, x,       S,  4096);

    // layernorm over channels
    ln_kernel<<<dim3(8192 / 64, NB), 256>>>(S, ln_g, ln_b, out, 8192);
}